// round 1
// baseline (speedup 1.0000x reference)
#include <cuda_runtime.h>
#include <cuda_bf16.h>
#include <math_constants.h>

// Problem constants
#define TT 2048
#define SS 2048
#define BB 8
#define EE 1024
#define HH 16
#define DD 64          // head dim
#define BH (BB*HH)     // 128
#define MM (TT*BB)     // 16384 rows for the big GEMMs
#define SCALE 0.125f   // D^-0.5 = 64^-0.5
#define EPS 1e-6f
#define HALF_PI 1.5707963267948966f

// -------- scratch (device globals; no allocation allowed) ----------
__device__ float g_Q[MM * EE];     // 64 MB
__device__ float g_K[MM * EE];
__device__ float g_V[MM * EE];
__device__ float g_O[MM * EE];
__device__ float g_KV[BH * 128 * DD];   // 4 MB  (per head: 2D x D)
__device__ float g_KSUM[BH * 128];

// ============================================================================
// SGEMM: C[M,N] = alpha * (A[M,K] @ W[N,K]^T + bias[N])
// Both A and W are K-contiguous (NT form). 128x128 tile, BK=8, 256 thr, 8x8/thr.
// ============================================================================
__global__ __launch_bounds__(256)
void sgemm_nt_bias(const float* __restrict__ A, const float* __restrict__ W,
                   const float* __restrict__ bias, float* __restrict__ C,
                   int M, int N, int K, float alpha) {
    __shared__ float As[8][128];
    __shared__ float Ws[8][128];

    const int tid = threadIdx.x;
    const int m0 = blockIdx.y * 128;
    const int n0 = blockIdx.x * 128;

    const int row = tid >> 1;            // 0..127
    const int seg = (tid & 1) * 4;       // 0 or 4
    const float* Ag = A + (size_t)(m0 + row) * K + seg;
    const float* Wg = W + (size_t)(n0 + row) * K + seg;

    const int ty = tid >> 4;             // 0..15 -> rows ty*8..
    const int tx = tid & 15;             // 0..15 -> cols tx*8..

    float acc[8][8];
#pragma unroll
    for (int i = 0; i < 8; i++)
#pragma unroll
        for (int j = 0; j < 8; j++) acc[i][j] = 0.f;

    for (int k0 = 0; k0 < K; k0 += 8) {
        const float4 av = *(const float4*)(Ag + k0);
        const float4 wv = *(const float4*)(Wg + k0);
        __syncthreads();
        As[seg + 0][row] = av.x; As[seg + 1][row] = av.y;
        As[seg + 2][row] = av.z; As[seg + 3][row] = av.w;
        Ws[seg + 0][row] = wv.x; Ws[seg + 1][row] = wv.y;
        Ws[seg + 2][row] = wv.z; Ws[seg + 3][row] = wv.w;
        __syncthreads();

#pragma unroll
        for (int kk = 0; kk < 8; kk++) {
            float a[8], b[8];
            *(float4*)(a)     = *(const float4*)&As[kk][ty * 8];
            *(float4*)(a + 4) = *(const float4*)&As[kk][ty * 8 + 4];
            *(float4*)(b)     = *(const float4*)&Ws[kk][tx * 8];
            *(float4*)(b + 4) = *(const float4*)&Ws[kk][tx * 8 + 4];
#pragma unroll
            for (int i = 0; i < 8; i++)
#pragma unroll
                for (int j = 0; j < 8; j++)
                    acc[i][j] = fmaf(a[i], b[j], acc[i][j]);
        }
    }

    // epilogue: alpha * (acc + bias)
#pragma unroll
    for (int i = 0; i < 8; i++) {
        const int m = m0 + ty * 8 + i;
#pragma unroll
        for (int j = 0; j < 8; j += 4) {
            const int n = n0 + tx * 8 + j;
            float4 o;
            o.x = alpha * (acc[i][j + 0] + bias[n + 0]);
            o.y = alpha * (acc[i][j + 1] + bias[n + 1]);
            o.z = alpha * (acc[i][j + 2] + bias[n + 2]);
            o.w = alpha * (acc[i][j + 3] + bias[n + 3]);
            *(float4*)&C[(size_t)m * N + n] = o;
        }
    }
}

// ============================================================================
// attn_kv: per head bh, kv[d2][e] = sum_s k2[s,d2] * v[s,e] ; ksum[d2]=sum_s k2
// k2[s,d2] = relu(k[s,d]) * (d2<64 ? sin_s : cos_s), d = d2 % 64
// grid = 128 (bh), 256 threads. Thread: 4 d2-rows x 8 e-cols.
// ============================================================================
__global__ __launch_bounds__(256)
void attn_kv_kernel(const float* __restrict__ Kp, const float* __restrict__ Vp,
                    float* __restrict__ KV, float* __restrict__ KSUM) {
    const int bh = blockIdx.x;
    const int b = bh / HH, h = bh % HH;
    const float* Kh = Kp + (size_t)b * EE + h * DD;   // + s*BB*EE
    const float* Vh = Vp + (size_t)b * EE + h * DD;

    __shared__ float ks[32][64];
    __shared__ float vs[32][64];
    __shared__ float ssin[32], scos[32];

    const int tid = threadIdx.x;
    const int ty = tid >> 3;            // 0..31 -> d2 rows ty*4..
    const int tx = tid & 7;             // 0..7  -> e cols tx*8..
    const int dbase = ty * 4;
    const bool hi = dbase >= 64;
    const int dloc = hi ? dbase - 64 : dbase;

    float acc[4][8];
#pragma unroll
    for (int i = 0; i < 4; i++)
#pragma unroll
        for (int j = 0; j < 8; j++) acc[i][j] = 0.f;
    float ksum[4] = {0.f, 0.f, 0.f, 0.f};

    for (int s0 = 0; s0 < SS; s0 += 32) {
        __syncthreads();
#pragma unroll
        for (int f = tid; f < 512; f += 256) {
            const int r = f >> 4;
            const int c = (f & 15) << 2;
            const size_t goff = (size_t)(s0 + r) * (BB * EE) + c;
            *(float4*)&ks[r][c] = *(const float4*)(Kh + goff);
            *(float4*)&vs[r][c] = *(const float4*)(Vh + goff);
        }
        if (tid < 32) {
            const float a = HALF_PI * (float)(s0 + tid + 1) * (1.0f / SS);
            ssin[tid] = __sinf(a);
            scos[tid] = __cosf(a);
        }
        __syncthreads();

#pragma unroll 4
        for (int s = 0; s < 32; s++) {
            const float f = hi ? scos[s] : ssin[s];
            const float4 kr = *(const float4*)&ks[s][dloc];
            float k2[4];
            k2[0] = fmaxf(kr.x, 0.f) * f;
            k2[1] = fmaxf(kr.y, 0.f) * f;
            k2[2] = fmaxf(kr.z, 0.f) * f;
            k2[3] = fmaxf(kr.w, 0.f) * f;
            ksum[0] += k2[0]; ksum[1] += k2[1];
            ksum[2] += k2[2]; ksum[3] += k2[3];
            float v[8];
            *(float4*)(v)     = *(const float4*)&vs[s][tx * 8];
            *(float4*)(v + 4) = *(const float4*)&vs[s][tx * 8 + 4];
#pragma unroll
            for (int i = 0; i < 4; i++)
#pragma unroll
                for (int j = 0; j < 8; j++)
                    acc[i][j] = fmaf(k2[i], v[j], acc[i][j]);
        }
    }

#pragma unroll
    for (int i = 0; i < 4; i++) {
        const int d2 = dbase + i;
        float* dst = KV + ((size_t)bh * 128 + d2) * DD + tx * 8;
        *(float4*)(dst)     = make_float4(acc[i][0], acc[i][1], acc[i][2], acc[i][3]);
        *(float4*)(dst + 4) = make_float4(acc[i][4], acc[i][5], acc[i][6], acc[i][7]);
        if (tx == 0) KSUM[bh * 128 + d2] = ksum[i];
    }
}

// ============================================================================
// attn_out: per (head, 64-row t-tile):
//   num[t,e] = sum_d2 q2[t,d2]*kv[d2,e];  den[t] = sum_d2 q2[t,d2]*ksum[d2]
//   O[t,b,h*D+e] = num/max(den,eps)
// grid = (128, 32), 256 threads. Thread: 4 t-rows x 4 e-cols.
// ============================================================================
__global__ __launch_bounds__(256)
void attn_out_kernel(const float* __restrict__ Qp, const float* __restrict__ KV,
                     const float* __restrict__ KSUM, float* __restrict__ O) {
    const int bh = blockIdx.x;
    const int b = bh / HH, h = bh % HH;
    const int t0 = blockIdx.y * 64;
    const float* Qh = Qp + (size_t)b * EE + h * DD;

    __shared__ float qs[64][64];       // relu(q) tile
    __shared__ float kvs[64][64];      // kv chunk (64 d2 x 64 e)
    __shared__ float tsin[64], tcos[64], dsh[64], kss[128];

    const int tid = threadIdx.x;

    // load q tile (relu applied)
#pragma unroll
    for (int f = tid; f < 1024; f += 256) {
        const int r = f >> 4;
        const int c = (f & 15) << 2;
        float4 q4 = *(const float4*)(Qh + (size_t)(t0 + r) * (BB * EE) + c);
        q4.x = fmaxf(q4.x, 0.f); q4.y = fmaxf(q4.y, 0.f);
        q4.z = fmaxf(q4.z, 0.f); q4.w = fmaxf(q4.w, 0.f);
        *(float4*)&qs[r][c] = q4;
    }
    if (tid < 64) {
        const float a = HALF_PI * (float)(t0 + tid + 1) * (1.0f / TT);
        tsin[tid] = __sinf(a);
        tcos[tid] = __cosf(a);
    }
    if (tid < 128) kss[tid] = KSUM[bh * 128 + tid];
    __syncthreads();

    // denominator per t row
    if (tid < 64) {
        const float sv = tsin[tid], cv = tcos[tid];
        float den = 0.f;
#pragma unroll 8
        for (int d = 0; d < 64; d++)
            den = fmaf(qs[tid][d], sv * kss[d] + cv * kss[64 + d], den);
        dsh[tid] = fmaxf(den, EPS);
    }

    const int ty = tid >> 4;   // 0..15 -> t rows ty*4..
    const int tx = tid & 15;   // 0..15 -> e cols tx*4..
    float acc[4][4];
#pragma unroll
    for (int i = 0; i < 4; i++)
#pragma unroll
        for (int j = 0; j < 4; j++) acc[i][j] = 0.f;

#pragma unroll
    for (int chunk = 0; chunk < 2; chunk++) {
        __syncthreads();
#pragma unroll
        for (int f = tid; f < 1024; f += 256) {
            const int r = f >> 4;
            const int c = (f & 15) << 2;
            *(float4*)&kvs[r][c] =
                *(const float4*)&KV[((size_t)bh * 128 + chunk * 64 + r) * DD + c];
        }
        __syncthreads();

        float fc[4];
#pragma unroll
        for (int i = 0; i < 4; i++) {
            const int t = ty * 4 + i;
            fc[i] = chunk ? tcos[t] : tsin[t];
        }
#pragma unroll 4
        for (int d2 = 0; d2 < 64; d2++) {
            float w[4];
#pragma unroll
            for (int i = 0; i < 4; i++)
                w[i] = qs[ty * 4 + i][d2] * fc[i];
            const float4 kv4 = *(const float4*)&kvs[d2][tx * 4];
#pragma unroll
            for (int i = 0; i < 4; i++) {
                acc[i][0] = fmaf(w[i], kv4.x, acc[i][0]);
                acc[i][1] = fmaf(w[i], kv4.y, acc[i][1]);
                acc[i][2] = fmaf(w[i], kv4.z, acc[i][2]);
                acc[i][3] = fmaf(w[i], kv4.w, acc[i][3]);
            }
        }
    }

#pragma unroll
    for (int i = 0; i < 4; i++) {
        const int t = ty * 4 + i;
        const float inv = 1.0f / dsh[t];
        float4 o;
        o.x = acc[i][0] * inv; o.y = acc[i][1] * inv;
        o.z = acc[i][2] * inv; o.w = acc[i][3] * inv;
        float* dst = O + (size_t)(t0 + t) * (BB * EE) + (size_t)b * EE + h * DD + tx * 4;
        *(float4*)dst = o;
    }
}

// ============================================================================
extern "C" void kernel_launch(void* const* d_in, const int* in_sizes, int n_in,
                              void* d_out, int out_size) {
    const float* query = (const float*)d_in[0];
    const float* key_in = (const float*)d_in[1];
    const float* value = (const float*)d_in[2];
    const float* wq = (const float*)d_in[3];
    const float* bq = (const float*)d_in[4];
    const float* wk = (const float*)d_in[5];
    const float* bk = (const float*)d_in[6];
    const float* wv = (const float*)d_in[7];
    const float* bv = (const float*)d_in[8];
    const float* wo = (const float*)d_in[9];
    const float* bo = (const float*)d_in[10];
    float* out = (float*)d_out;

    float *Q, *K, *V, *O, *KV, *KSUM;
    cudaGetSymbolAddress((void**)&Q, g_Q);
    cudaGetSymbolAddress((void**)&K, g_K);
    cudaGetSymbolAddress((void**)&V, g_V);
    cudaGetSymbolAddress((void**)&O, g_O);
    cudaGetSymbolAddress((void**)&KV, g_KV);
    cudaGetSymbolAddress((void**)&KSUM, g_KSUM);

    const dim3 gemm_grid(EE / 128, MM / 128);   // (8, 128)
    const dim3 gemm_blk(256);

    // projections (q scaled by D^-0.5)
    sgemm_nt_bias<<<gemm_grid, gemm_blk>>>(query, wq, bq, Q, MM, EE, EE, SCALE);
    sgemm_nt_bias<<<gemm_grid, gemm_blk>>>(key_in, wk, bk, K, MM, EE, EE, 1.0f);
    sgemm_nt_bias<<<gemm_grid, gemm_blk>>>(value, wv, bv, V, MM, EE, EE, 1.0f);

    // linear attention core
    attn_kv_kernel<<<BH, 256>>>(K, V, KV, KSUM);
    attn_out_kernel<<<dim3(BH, TT / 64), 256>>>(Q, KV, KSUM, O);

    // output projection straight into d_out
    sgemm_nt_bias<<<gemm_grid, gemm_blk>>>(O, wo, bo, out, MM, EE, EE, 1.0f);
}

// round 3
// speedup vs baseline: 3.1143x; 3.1143x over previous
#include <cuda_runtime.h>
#include <cuda_bf16.h>
#include <cstdint>

// ---------------- problem constants ----------------
#define TT 2048
#define SS 2048
#define BB 8
#define EE 1024
#define HH 16
#define DD 64
#define BH (BB*HH)     // 128
#define MM (TT*BB)     // 16384
#define SCALE 0.125f
#define EPS 1e-6f
#define HALF_PI 1.5707963267948966f
#define KSPLIT 4

// ---------------- scratch ----------------
__device__ float g_Q[MM * EE];
__device__ float g_K[MM * EE];
__device__ float g_V[MM * EE];
__device__ float g_O[MM * EE];
__device__ float g_R[MM * EE];          // rounded activation staging
__device__ float g_RW[EE * EE];         // rounded weight staging
__device__ float g_KVp[KSPLIT * BH * 128 * DD];
__device__ float g_KSUMp[KSPLIT * BH * 128];
__device__ float g_KV[BH * 128 * DD];

// ---------------- helpers ----------------
__device__ __forceinline__ uint32_t smem_u32(const void* p) {
    uint32_t a;
    asm("{ .reg .u64 t; cvta.to.shared.u64 t, %1; cvt.u32.u64 %0, t; }" : "=r"(a) : "l"(p));
    return a;
}
__device__ __forceinline__ void cp16(uint32_t sdst, const void* g) {
    asm volatile("cp.async.cg.shared.global [%0], [%1], 16;" :: "r"(sdst), "l"(g));
}
__device__ __forceinline__ uint32_t lds32(uint32_t addr) {
    uint32_t v;
    asm volatile("ld.shared.b32 %0, [%1];" : "=r"(v) : "r"(addr));
    return v;
}
__device__ __forceinline__ float tf32_rna(float x) {
    uint32_t u;
    asm("cvt.rna.tf32.f32 %0, %1;" : "=r"(u) : "f"(x));
    return __uint_as_float(u);
}
__device__ __forceinline__ void mma_tf32(float d[4], const uint32_t a[4], const uint32_t b[2]) {
    asm volatile(
        "mma.sync.aligned.m16n8k8.row.col.f32.tf32.tf32.f32 "
        "{%0,%1,%2,%3}, {%4,%5,%6,%7}, {%8,%9}, {%0,%1,%2,%3};"
        : "+f"(d[0]), "+f"(d[1]), "+f"(d[2]), "+f"(d[3])
        : "r"(a[0]), "r"(a[1]), "r"(a[2]), "r"(a[3]), "r"(b[0]), "r"(b[1]));
}

// ============================================================================
// tf32 mma.sync GEMM: C[M,N] = alpha*(A[M,K] @ W[N,K]^T + bias[N])
// M=16384, N=K=1024. Tile 128x128xBK32, 256 thr (8 warps, 2x4), warp=64x32.
// SMEM: [row][32 floats] per chunk, float4-column swizzle kg^(row&7).
// 3-stage cp.async pipeline. Inputs must be pre-rounded to tf32.
// ============================================================================
#define STAGE_BYTES 32768                 // A 16KB + B 16KB
#define G_SMEM (3 * STAGE_BYTES)

__global__ __launch_bounds__(256)
void gemm_tf32mma(const float* __restrict__ A, const float* __restrict__ W,
                  const float* __restrict__ bias, float* __restrict__ C, float alpha) {
    extern __shared__ char smem[];
    const uint32_t sb = smem_u32(smem);
    const int tid = threadIdx.x;
    const int lane = tid & 31, wid = tid >> 5;
    const int wm = wid & 1, wn = wid >> 1;
    const int kq = lane & 3, s = lane >> 2;
    const int m0 = blockIdx.y * 128, n0 = blockIdx.x * 128;

    float acc[4][4][4];
#pragma unroll
    for (int i = 0; i < 4; i++)
#pragma unroll
        for (int j = 0; j < 4; j++)
#pragma unroll
            for (int r = 0; r < 4; r++) acc[i][j][r] = 0.f;

    auto load_chunk = [&](int c, int st) {
        const uint32_t stA = sb + st * STAGE_BYTES;
        const uint32_t stB = stA + 16384;
        const int kc = c * 32;
#pragma unroll
        for (int it = 0; it < 4; ++it) {
            const int idx = it * 256 + tid;           // 0..1023
            const int m = idx >> 3, kg = idx & 7;
            const uint32_t soff = (uint32_t)(m * 128 + ((kg ^ (m & 7)) << 4));
            cp16(stA + soff, &A[(size_t)(m0 + m) * EE + kc + kg * 4]);
            cp16(stB + soff, &W[(size_t)(n0 + m) * EE + kc + kg * 4]);
        }
        asm volatile("cp.async.commit_group;" ::: "memory");
    };

    load_chunk(0, 0);
    load_chunk(1, 1);

    for (int c = 0; c < 32; ++c) {
        if (c < 31) asm volatile("cp.async.wait_group 1;" ::: "memory");
        else        asm volatile("cp.async.wait_group 0;" ::: "memory");
        __syncthreads();
        if (c + 2 < 32) load_chunk(c + 2, (c + 2) % 3);

        const int st = c % 3;
        const uint32_t stA = sb + st * STAGE_BYTES;
        const uint32_t stB = stA + 16384;
        const uint32_t aBase = stA + (uint32_t)((wm * 64 + s) * 128 + kq * 4);
        const uint32_t bBase = stB + (uint32_t)((wn * 32 + s) * 128 + kq * 4);

#pragma unroll
        for (int k8 = 0; k8 < 4; ++k8) {
            const uint32_t c0 = (uint32_t)(((k8 * 2 + 0) ^ s) << 4);
            const uint32_t c1 = (uint32_t)(((k8 * 2 + 1) ^ s) << 4);
            uint32_t a[4][4];
#pragma unroll
            for (int mi = 0; mi < 4; ++mi) {
                a[mi][0] = lds32(aBase + c0 + mi * 2048);
                a[mi][1] = lds32(aBase + c0 + mi * 2048 + 1024);
                a[mi][2] = lds32(aBase + c1 + mi * 2048);
                a[mi][3] = lds32(aBase + c1 + mi * 2048 + 1024);
            }
            uint32_t b[4][2];
#pragma unroll
            for (int ni = 0; ni < 4; ++ni) {
                b[ni][0] = lds32(bBase + c0 + ni * 1024);
                b[ni][1] = lds32(bBase + c1 + ni * 1024);
            }
#pragma unroll
            for (int mi = 0; mi < 4; ++mi)
#pragma unroll
                for (int ni = 0; ni < 4; ++ni)
                    mma_tf32(acc[mi][ni], a[mi], b[ni]);
        }
    }

    // epilogue: alpha*(acc + bias), direct global float2 stores (32B sectors)
#pragma unroll
    for (int mi = 0; mi < 4; ++mi) {
        const int m = m0 + wm * 64 + mi * 16 + s;
#pragma unroll
        for (int ni = 0; ni < 4; ++ni) {
            const int n = n0 + wn * 32 + ni * 8 + kq * 2;
            const float2 bi = *(const float2*)&bias[n];
            float2 o0, o1;
            o0.x = alpha * (acc[mi][ni][0] + bi.x);
            o0.y = alpha * (acc[mi][ni][1] + bi.y);
            o1.x = alpha * (acc[mi][ni][2] + bi.x);
            o1.y = alpha * (acc[mi][ni][3] + bi.y);
            *(float2*)&C[(size_t)m * EE + n] = o0;
            *(float2*)&C[(size_t)(m + 8) * EE + n] = o1;
        }
    }
}

// ============================================================================
// rounding pass: out[i] = round_to_nearest_tf32(in[i])
// ============================================================================
__global__ __launch_bounds__(256)
void round_tf32_kernel(const float* __restrict__ in, float* __restrict__ out, int n4) {
    const int i = blockIdx.x * 256 + threadIdx.x;
    if (i < n4) {
        float4 v = ((const float4*)in)[i];
        v.x = tf32_rna(v.x); v.y = tf32_rna(v.y);
        v.z = tf32_rna(v.z); v.w = tf32_rna(v.w);
        ((float4*)out)[i] = v;
    }
}

// ============================================================================
// attn_kv (split over S by KSPLIT): partial kv / ksum per split
// ============================================================================
__global__ __launch_bounds__(256)
void attn_kv_kernel(const float* __restrict__ Kp, const float* __restrict__ Vp,
                    float* __restrict__ KVp, float* __restrict__ KSUMp) {
    const int bh = blockIdx.x;
    const int sp = blockIdx.y;
    const int b = bh / HH, h = bh % HH;
    const float* Kh = Kp + (size_t)b * EE + h * DD;
    const float* Vh = Vp + (size_t)b * EE + h * DD;

    __shared__ float ks[32][64];
    __shared__ float vs[32][64];
    __shared__ float ssin[32], scos[32];

    const int tid = threadIdx.x;
    const int ty = tid >> 3;
    const int tx = tid & 7;
    const int dbase = ty * 4;
    const bool hi = dbase >= 64;
    const int dloc = hi ? dbase - 64 : dbase;

    float acc[4][8];
#pragma unroll
    for (int i = 0; i < 4; i++)
#pragma unroll
        for (int j = 0; j < 8; j++) acc[i][j] = 0.f;
    float ksum[4] = {0.f, 0.f, 0.f, 0.f};

    const int sbeg = sp * (SS / KSPLIT), send = sbeg + SS / KSPLIT;
    for (int s0 = sbeg; s0 < send; s0 += 32) {
        __syncthreads();
#pragma unroll
        for (int f = tid; f < 512; f += 256) {
            const int r = f >> 4;
            const int c = (f & 15) << 2;
            const size_t goff = (size_t)(s0 + r) * (BB * EE) + c;
            *(float4*)&ks[r][c] = *(const float4*)(Kh + goff);
            *(float4*)&vs[r][c] = *(const float4*)(Vh + goff);
        }
        if (tid < 32) {
            const float a = HALF_PI * (float)(s0 + tid + 1) * (1.0f / SS);
            ssin[tid] = __sinf(a);
            scos[tid] = __cosf(a);
        }
        __syncthreads();

#pragma unroll 4
        for (int sI = 0; sI < 32; sI++) {
            const float f = hi ? scos[sI] : ssin[sI];
            const float4 kr = *(const float4*)&ks[sI][dloc];
            float k2[4];
            k2[0] = fmaxf(kr.x, 0.f) * f;
            k2[1] = fmaxf(kr.y, 0.f) * f;
            k2[2] = fmaxf(kr.z, 0.f) * f;
            k2[3] = fmaxf(kr.w, 0.f) * f;
            ksum[0] += k2[0]; ksum[1] += k2[1];
            ksum[2] += k2[2]; ksum[3] += k2[3];
            float v[8];
            *(float4*)(v)     = *(const float4*)&vs[sI][tx * 8];
            *(float4*)(v + 4) = *(const float4*)&vs[sI][tx * 8 + 4];
#pragma unroll
            for (int i = 0; i < 4; i++)
#pragma unroll
                for (int j = 0; j < 8; j++)
                    acc[i][j] = fmaf(k2[i], v[j], acc[i][j]);
        }
    }

    float* KVo = KVp + (size_t)sp * BH * 128 * DD;
#pragma unroll
    for (int i = 0; i < 4; i++) {
        const int d2 = dbase + i;
        float* dst = KVo + ((size_t)bh * 128 + d2) * DD + tx * 8;
        *(float4*)(dst)     = make_float4(acc[i][0], acc[i][1], acc[i][2], acc[i][3]);
        *(float4*)(dst + 4) = make_float4(acc[i][4], acc[i][5], acc[i][6], acc[i][7]);
        if (tx == 0) KSUMp[(size_t)sp * BH * 128 + bh * 128 + d2] = ksum[i];
    }
}

// sum KSPLIT partial KV planes
__global__ __launch_bounds__(256)
void kv_reduce_kernel(const float* __restrict__ KVp, float* __restrict__ KV) {
    const int i = blockIdx.x * 256 + threadIdx.x;
    const size_t plane = (size_t)BH * 128 * DD / 4;
    float4 a = ((const float4*)KVp)[i];
    const float4 b = ((const float4*)KVp)[plane + i];
    const float4 c = ((const float4*)KVp)[2 * plane + i];
    const float4 d = ((const float4*)KVp)[3 * plane + i];
    a.x += b.x + c.x + d.x; a.y += b.y + c.y + d.y;
    a.z += b.z + c.z + d.z; a.w += b.w + c.w + d.w;
    ((float4*)KV)[i] = a;
}

// ============================================================================
// attn_out: num/den + output (stores tf32-rounded, feeds final GEMM)
// ============================================================================
__global__ __launch_bounds__(256)
void attn_out_kernel(const float* __restrict__ Qp, const float* __restrict__ KV,
                     const float* __restrict__ KSUMp, float* __restrict__ O) {
    const int bh = blockIdx.x;
    const int b = bh / HH, h = bh % HH;
    const int t0 = blockIdx.y * 64;
    const float* Qh = Qp + (size_t)b * EE + h * DD;

    __shared__ float qs[64][64];
    __shared__ float kvs[64][64];
    __shared__ float tsin[64], tcos[64], dsh[64], kss[128];

    const int tid = threadIdx.x;

#pragma unroll
    for (int f = tid; f < 1024; f += 256) {
        const int r = f >> 4;
        const int c = (f & 15) << 2;
        float4 q4 = *(const float4*)(Qh + (size_t)(t0 + r) * (BB * EE) + c);
        q4.x = fmaxf(q4.x, 0.f); q4.y = fmaxf(q4.y, 0.f);
        q4.z = fmaxf(q4.z, 0.f); q4.w = fmaxf(q4.w, 0.f);
        *(float4*)&qs[r][c] = q4;
    }
    if (tid < 64) {
        const float a = HALF_PI * (float)(t0 + tid + 1) * (1.0f / TT);
        tsin[tid] = __sinf(a);
        tcos[tid] = __cosf(a);
    }
    if (tid < 128) {
        const size_t pl = (size_t)BH * 128;
        const size_t off = (size_t)bh * 128 + tid;
        kss[tid] = KSUMp[off] + KSUMp[pl + off] + KSUMp[2 * pl + off] + KSUMp[3 * pl + off];
    }
    __syncthreads();

    if (tid < 64) {
        const float sv = tsin[tid], cv = tcos[tid];
        float den = 0.f;
#pragma unroll 8
        for (int d = 0; d < 64; d++)
            den = fmaf(qs[tid][d], sv * kss[d] + cv * kss[64 + d], den);
        dsh[tid] = fmaxf(den, EPS);
    }

    const int ty = tid >> 4;
    const int tx = tid & 15;
    float acc[4][4];
#pragma unroll
    for (int i = 0; i < 4; i++)
#pragma unroll
        for (int j = 0; j < 4; j++) acc[i][j] = 0.f;

#pragma unroll
    for (int chunk = 0; chunk < 2; chunk++) {
        __syncthreads();
#pragma unroll
        for (int f = tid; f < 1024; f += 256) {
            const int r = f >> 4;
            const int c = (f & 15) << 2;
            *(float4*)&kvs[r][c] =
                *(const float4*)&KV[((size_t)bh * 128 + chunk * 64 + r) * DD + c];
        }
        __syncthreads();

        float fc[4];
#pragma unroll
        for (int i = 0; i < 4; i++) {
            const int t = ty * 4 + i;
            fc[i] = chunk ? tcos[t] : tsin[t];
        }
#pragma unroll 4
        for (int d2 = 0; d2 < 64; d2++) {
            float w[4];
#pragma unroll
            for (int i = 0; i < 4; i++)
                w[i] = qs[ty * 4 + i][d2] * fc[i];
            const float4 kv4 = *(const float4*)&kvs[d2][tx * 4];
#pragma unroll
            for (int i = 0; i < 4; i++) {
                acc[i][0] = fmaf(w[i], kv4.x, acc[i][0]);
                acc[i][1] = fmaf(w[i], kv4.y, acc[i][1]);
                acc[i][2] = fmaf(w[i], kv4.z, acc[i][2]);
                acc[i][3] = fmaf(w[i], kv4.w, acc[i][3]);
            }
        }
    }

#pragma unroll
    for (int i = 0; i < 4; i++) {
        const int t = ty * 4 + i;
        const float inv = 1.0f / dsh[t];
        float4 o;
        o.x = tf32_rna(acc[i][0] * inv); o.y = tf32_rna(acc[i][1] * inv);
        o.z = tf32_rna(acc[i][2] * inv); o.w = tf32_rna(acc[i][3] * inv);
        float* dst = O + (size_t)(t0 + t) * (BB * EE) + (size_t)b * EE + h * DD + tx * 4;
        *(float4*)dst = o;
    }
}

// ============================================================================
extern "C" void kernel_launch(void* const* d_in, const int* in_sizes, int n_in,
                              void* d_out, int out_size) {
    const float* query  = (const float*)d_in[0];
    const float* key_in = (const float*)d_in[1];
    const float* value  = (const float*)d_in[2];
    const float* wq = (const float*)d_in[3];
    const float* bq = (const float*)d_in[4];
    const float* wk = (const float*)d_in[5];
    const float* bk = (const float*)d_in[6];
    const float* wv = (const float*)d_in[7];
    const float* bv = (const float*)d_in[8];
    const float* wo = (const float*)d_in[9];
    const float* bo = (const float*)d_in[10];
    float* out = (float*)d_out;

    float *Q, *K, *V, *O, *R, *RW, *KVp, *KSUMp, *KV;
    cudaGetSymbolAddress((void**)&Q, g_Q);
    cudaGetSymbolAddress((void**)&K, g_K);
    cudaGetSymbolAddress((void**)&V, g_V);
    cudaGetSymbolAddress((void**)&O, g_O);
    cudaGetSymbolAddress((void**)&R, g_R);
    cudaGetSymbolAddress((void**)&RW, g_RW);
    cudaGetSymbolAddress((void**)&KVp, g_KVp);
    cudaGetSymbolAddress((void**)&KSUMp, g_KSUMp);
    cudaGetSymbolAddress((void**)&KV, g_KV);

    cudaFuncSetAttribute(gemm_tf32mma, cudaFuncAttributeMaxDynamicSharedMemorySize, G_SMEM);

    const dim3 ggrid(EE / 128, MM / 128);     // (8, 128)
    const int act4 = MM * EE / 4;
    const int w4 = EE * EE / 4;

    // q projection
    round_tf32_kernel<<<(act4 + 255) / 256, 256>>>(query, R, act4);
    round_tf32_kernel<<<(w4 + 255) / 256, 256>>>(wq, RW, w4);
    gemm_tf32mma<<<ggrid, 256, G_SMEM>>>(R, RW, bq, Q, SCALE);
    // k projection
    round_tf32_kernel<<<(act4 + 255) / 256, 256>>>(key_in, R, act4);
    round_tf32_kernel<<<(w4 + 255) / 256, 256>>>(wk, RW, w4);
    gemm_tf32mma<<<ggrid, 256, G_SMEM>>>(R, RW, bk, K, 1.0f);
    // v projection
    round_tf32_kernel<<<(act4 + 255) / 256, 256>>>(value, R, act4);
    round_tf32_kernel<<<(w4 + 255) / 256, 256>>>(wv, RW, w4);
    gemm_tf32mma<<<ggrid, 256, G_SMEM>>>(R, RW, bv, V, 1.0f);

    // linear attention core
    attn_kv_kernel<<<dim3(BH, KSPLIT), 256>>>(K, V, KVp, KSUMp);
    kv_reduce_kernel<<<BH * 128 * DD / 4 / 256, 256>>>(KVp, KV);
    attn_out_kernel<<<dim3(BH, TT / 64), 256>>>(Q, KV, KSUMp, O);

    // output projection (O already tf32-rounded at store)
    round_tf32_kernel<<<(w4 + 255) / 256, 256>>>(wo, RW, w4);
    gemm_tf32mma<<<ggrid, 256, G_SMEM>>>(O, RW, bo, out, 1.0f);
}